// round 2
// baseline (speedup 1.0000x reference)
#include <cuda_runtime.h>
#include <cstdint>

// Problem constants
#define BB 16
#define NN 12800
#define FM 128          // F_MSG
#define FN 256          // F_NODE
#define NBINS 100       // N / BIN_SIZE
#define HB 50           // NBINS / 2
#define BS 128          // BIN_SIZE
#define NKEYS 200       // bin keys in [0, 198]
#define ROTC 100        // rot second-dim stride (MAX_NUM_BINS/2)

// Output layout (flattened float32, reference tuple order)
#define OFF_BINS   0
#define LEN_BINS   (BB * NN)                  // 204800
#define OFF_XNODE  (OFF_BINS + LEN_BINS)      // 204800
#define LEN_XNODE  (BB * NN * FN)             // 52428800
#define OFF_DM     (OFF_XNODE + LEN_XNODE)    // 52633600
#define LEN_DM     (BB * NN * BS)             // 26214400
#define OFF_MSKF   (OFF_DM + LEN_DM)          // 78848000

// Scratch (device globals: no allocation allowed)
__device__ int g_key[BB * NN];    // bin key per (b,n)
__device__ int g_bins[BB * NN];   // sorted original indices (bins_split)

__device__ __forceinline__ float ex2f(float x) {
    float y; asm("ex2.approx.f32 %0, %1;" : "=f"(y) : "f"(x)); return y;
}
__device__ __forceinline__ float rsqf(float x) {
    float y; asm("rsqrt.approx.f32 %0, %1;" : "=f"(y) : "f"(x)); return y;
}

// ---------------------------------------------------------------------------
// K1: LSH projection + argmax -> bin key.
// One block of 128 threads handles 128 nodes of one batch.
// smem: Xs[128][129] (node tile) + Rs[128][50] (rot columns 0..49).
// ---------------------------------------------------------------------------
__global__ void k_proj(const float* __restrict__ x_msg,
                       const int* __restrict__ msk,
                       const float* __restrict__ rot) {
    const int b    = blockIdx.x / (NN / 128);
    const int tile = blockIdx.x % (NN / 128);
    const int n0   = tile * 128;
    extern __shared__ float sm1[];
    float* Xs = sm1;                 // 128*129
    float* Rs = sm1 + 128 * 129;     // 128*50
    const int tid = threadIdx.x;     // 128 threads

    for (int idx = tid; idx < 128 * HB; idx += 128) {
        int f = idx / HB, h = idx % HB;
        Rs[idx] = rot[f * ROTC + h];
    }
    const float* xb = x_msg + ((size_t)b * NN + n0) * FM;
    for (int idx = tid; idx < 128 * FM; idx += 128) {
        int r = idx >> 7, f = idx & 127;
        Xs[r * 129 + f] = xb[idx];
    }
    __syncthreads();

    float acc[HB];
#pragma unroll
    for (int h = 0; h < HB; h++) acc[h] = 0.f;
    const float* xr = Xs + tid * 129;
    for (int f = 0; f < FM; f++) {
        float xv = xr[f];
        const float* rp = Rs + f * HB;
#pragma unroll
        for (int h = 0; h < HB; h++) acc[h] = fmaf(xv, rp[h], acc[h]);
    }

    // argmax over cmul = [mul, -mul] with first-occurrence tie rule
    float bv = acc[0]; int bh = 0;
    float mv = acc[0]; int mh = 0;
#pragma unroll
    for (int h = 1; h < HB; h++) {
        if (acc[h] > bv) { bv = acc[h]; bh = h; }
        if (acc[h] < mv) { mv = acc[h]; mh = h; }
    }
    int idx = (bv >= -mv) ? bh : (HB + mh);

    const int n = n0 + tid;
    const int m = msk[(size_t)b * NN + n];
    g_key[(size_t)b * NN + n] = idx + (m ? 0 : (NBINS - 1));
}

// ---------------------------------------------------------------------------
// K2: stable counting sort per batch (matches stable jnp.argsort).
// 16 blocks x 128 threads; thread t owns contiguous chunk of 100 items.
// Also writes bins_split (as float) and msk_f_binned directly to d_out.
// dyn smem: u16 off[NKEYS][128] = 51200 B.
// ---------------------------------------------------------------------------
__global__ void k_sort(const int* __restrict__ msk,
                       float* __restrict__ out) {
    const int b = blockIdx.x;
    extern __shared__ unsigned short off[];        // [NKEYS][128]
    __shared__ unsigned int keyTotal[NKEYS];
    __shared__ unsigned int keyBase[NKEYS];
    const int t = threadIdx.x;                     // 128 threads

    for (int i = t; i < NKEYS * 128; i += 128) off[i] = 0;
    __syncthreads();

    const int* kb = g_key + (size_t)b * NN;
    const int base_n = t * 100;
    for (int q = 0; q < 100; q++) {
        int k = kb[base_n + q];
        off[k * 128 + t]++;
    }
    __syncthreads();

    for (int k = t; k < NKEYS; k += 128) {
        unsigned int run = 0;
        for (int tt = 0; tt < 128; tt++) {
            unsigned short c = off[k * 128 + tt];
            off[k * 128 + tt] = (unsigned short)run;
            run += c;
        }
        keyTotal[k] = run;
    }
    __syncthreads();
    if (t == 0) {
        unsigned int run = 0;
        for (int k = 0; k < NKEYS; k++) { keyBase[k] = run; run += keyTotal[k]; }
    }
    __syncthreads();

    int* gb = g_bins + (size_t)b * NN;
    const int* mb = msk + (size_t)b * NN;
    float* out_bins = out + OFF_BINS + (size_t)b * NN;
    float* out_mskf = out + OFF_MSKF + (size_t)b * NN;
    for (int q = 0; q < 100; q++) {
        int n = base_n + q;
        int k = kb[n];
        unsigned int pos = keyBase[k] + off[k * 128 + t];
        off[k * 128 + t]++;
        gb[pos] = n;
        out_bins[pos] = (float)n;
        out_mskf[pos] = mb[n] ? 1.0f : 0.0f;
    }
}

// ---------------------------------------------------------------------------
// K3: gather x_node rows (float4, coalesced).
// ---------------------------------------------------------------------------
__global__ void k_gather(const float4* __restrict__ x_node4,
                         float4* __restrict__ out4) {
    const size_t idx = (size_t)blockIdx.x * 256 + threadIdx.x; // B*N*64
    const int row = (int)(idx >> 6);       // b*N + pos
    const int f4  = (int)(idx & 63);
    const int b   = row / NN;
    const int src = g_bins[row];
    out4[idx] = x_node4[((size_t)b * NN + src) * (FN / 4) + f4];
}

// ---------------------------------------------------------------------------
// K4: per-bin pairwise gaussian kernel.
// One block (16x16 threads) per (b, bin). A^T staged in smem [f][i] (stride
// 132), gram via 8x8 register tiles, epilogue sqrt/exp via MUFU approx.
// dyn smem: 128*132*4 + 2*128*4 = 68608 B.
// ---------------------------------------------------------------------------
#define ST 132
__global__ void k_dm(const float4* __restrict__ x_msg4,
                     const int* __restrict__ msk,
                     float* __restrict__ dm_out) {
    const int b   = blockIdx.x / NBINS;
    const int bin = blockIdx.x % NBINS;
    extern __shared__ float sm4[];
    float* As = sm4;                 // [128][ST], f-major (A transposed)
    float* na = sm4 + 128 * ST;      // [128]
    float* mm = na + 128;            // [128]
    const int tid  = threadIdx.x;    // 256
    const int w    = tid >> 5;
    const int lane = tid & 31;

    const int* gb = g_bins + ((size_t)b * NBINS + bin) * BS;
    const float4* xb = x_msg4 + (size_t)b * NN * (FM / 4);
    for (int r = w; r < BS; r += 8) {
        int src = gb[r];
        float m = msk[(size_t)b * NN + src] ? 1.f : 0.f;
        float4 v = xb[(size_t)src * (FM / 4) + lane];
        v.x *= m; v.y *= m; v.z *= m; v.w *= m;
        As[(4 * lane + 0) * ST + r] = v.x;
        As[(4 * lane + 1) * ST + r] = v.y;
        As[(4 * lane + 2) * ST + r] = v.z;
        As[(4 * lane + 3) * ST + r] = v.w;
        float s = v.x * v.x + v.y * v.y + v.z * v.z + v.w * v.w;
#pragma unroll
        for (int o = 16; o; o >>= 1) s += __shfl_xor_sync(0xffffffffu, s, o);
        if (lane == 0) { na[r] = s; mm[r] = m; }
    }
    __syncthreads();

    const int tx = tid & 15, ty = tid >> 4;
    const int i0 = ty * 8, j0 = tx * 8;
    float acc[8][8];
#pragma unroll
    for (int u = 0; u < 8; u++)
#pragma unroll
        for (int v = 0; v < 8; v++) acc[u][v] = 0.f;

    for (int f = 0; f < FM; f++) {
        const float* row = As + f * ST;
        float4 a0 = *(const float4*)(row + i0);
        float4 a1 = *(const float4*)(row + i0 + 4);
        float4 b0 = *(const float4*)(row + j0);
        float4 b1 = *(const float4*)(row + j0 + 4);
        float a[8] = {a0.x, a0.y, a0.z, a0.w, a1.x, a1.y, a1.z, a1.w};
        float bvv[8] = {b0.x, b0.y, b0.z, b0.w, b1.x, b1.y, b1.z, b1.w};
#pragma unroll
        for (int u = 0; u < 8; u++)
#pragma unroll
            for (int v = 0; v < 8; v++) acc[u][v] = fmaf(a[u], bvv[v], acc[u][v]);
    }

    float nai[8], mi[8], naj[8], mj[8];
#pragma unroll
    for (int u = 0; u < 8; u++) { nai[u] = na[i0 + u]; mi[u] = mm[i0 + u]; }
#pragma unroll
    for (int v = 0; v < 8; v++) { naj[v] = na[j0 + v]; mj[v] = mm[j0 + v]; }

    float* dout = dm_out + (size_t)blockIdx.x * BS * BS;
    const float c = -0.14426950408889634f;   // -DIST_MULT * log2(e)
#pragma unroll
    for (int u = 0; u < 8; u++) {
        float res[8];
#pragma unroll
        for (int v = 0; v < 8; v++) {
            float x = fmaxf(nai[u] + naj[v] - 2.0f * acc[u][v], 1e-6f);
            float d = x * rsqf(x);            // sqrt(x), x >= 1e-6
            float val = ex2f(c * d) * mi[u] * mj[v];
            res[v] = fminf(val, 1.0f);
        }
        float4* p = (float4*)(dout + (i0 + u) * BS + j0);
        p[0] = make_float4(res[0], res[1], res[2], res[3]);
        p[1] = make_float4(res[4], res[5], res[6], res[7]);
    }
}

// ---------------------------------------------------------------------------
extern "C" void kernel_launch(void* const* d_in, const int* in_sizes, int n_in,
                              void* d_out, int out_size) {
    const float* x_msg  = (const float*)d_in[0];
    const float* x_node = (const float*)d_in[1];
    const int*   msk    = (const int*)d_in[2];
    const float* rot    = (const float*)d_in[3];
    float* out = (float*)d_out;

    const int SM1 = 128 * 129 * 4 + 128 * HB * 4;   // 91648
    const int SM2 = NKEYS * 128 * 2;                // 51200
    const int SM4 = 128 * ST * 4 + 2 * 128 * 4;     // 68608
    cudaFuncSetAttribute(k_proj, cudaFuncAttributeMaxDynamicSharedMemorySize, SM1);
    cudaFuncSetAttribute(k_sort, cudaFuncAttributeMaxDynamicSharedMemorySize, SM2);
    cudaFuncSetAttribute(k_dm,   cudaFuncAttributeMaxDynamicSharedMemorySize, SM4);

    k_proj<<<BB * (NN / 128), 128, SM1>>>(x_msg, msk, rot);
    k_sort<<<BB, 128, SM2>>>(msk, out);
    k_gather<<<(BB * NN * (FN / 4)) / 256, 256>>>(
        (const float4*)x_node, (float4*)(out + OFF_XNODE));
    k_dm<<<BB * NBINS, 256, SM4>>>((const float4*)x_msg, msk, out + OFF_DM);
}

// round 3
// speedup vs baseline: 1.0873x; 1.0873x over previous
#include <cuda_runtime.h>
#include <cstdint>

// Problem constants
#define BB 16
#define NN 12800
#define FM 128          // F_MSG
#define FN 256          // F_NODE
#define NBINS 100       // N / BIN_SIZE
#define HB 50           // NBINS / 2
#define BS 128          // BIN_SIZE
#define NKEYS 200       // bin keys in [0, 198]
#define ROTC 100        // rot second-dim stride (MAX_NUM_BINS/2)

// Output layout (flattened float32, reference tuple order)
#define OFF_BINS   0
#define LEN_BINS   (BB * NN)                  // 204800
#define OFF_XNODE  (OFF_BINS + LEN_BINS)      // 204800
#define LEN_XNODE  (BB * NN * FN)             // 52428800
#define OFF_DM     (OFF_XNODE + LEN_XNODE)    // 52633600
#define LEN_DM     (BB * NN * BS)             // 26214400
#define OFF_MSKF   (OFF_DM + LEN_DM)          // 78848000

// Scratch (device globals: no allocation allowed)
__device__ int g_key[BB * NN];    // bin key per (b,n)
__device__ int g_bins[BB * NN];   // sorted original indices (bins_split)

typedef unsigned long long u64;

__device__ __forceinline__ float ex2f(float x) {
    float y; asm("ex2.approx.f32 %0, %1;" : "=f"(y) : "f"(x)); return y;
}
__device__ __forceinline__ float rsqf(float x) {
    float y; asm("rsqrt.approx.f32 %0, %1;" : "=f"(y) : "f"(x)); return y;
}
// packed fp32x2 helpers (bit-exact per-lane IEEE fp32 FMA)
__device__ __forceinline__ u64 pack2(float x, float y) {
    u64 r; asm("mov.b64 %0, {%1, %2};" : "=l"(r) : "f"(x), "f"(y)); return r;
}
__device__ __forceinline__ void unpack2(u64 v, float& x, float& y) {
    asm("mov.b64 {%0, %1}, %2;" : "=f"(x), "=f"(y) : "l"(v));
}
__device__ __forceinline__ void fma2(u64& d, u64 a, u64 b) {
    asm("fma.rn.f32x2 %0, %1, %2, %0;" : "+l"(d) : "l"(a), "l"(b));
}

// ---------------------------------------------------------------------------
// K1: LSH projection + argmax -> bin key.
// One block of 128 threads handles 128 nodes of one batch.
// smem: Xs[128][132] (node tile, f4-aligned) + Rs[128][52] (rot, pair-packed).
// Inner loop per f: 12x LDS.128 + 1x LDS.64 (rot, broadcast) + 25 FFMA2.
// ---------------------------------------------------------------------------
#define XST 132
#define RST 52
__global__ void __launch_bounds__(128, 2)
k_proj(const float* __restrict__ x_msg,
       const int* __restrict__ msk,
       const float* __restrict__ rot) {
    const int b    = blockIdx.x / (NN / 128);
    const int tile = blockIdx.x % (NN / 128);
    const int n0   = tile * 128;
    extern __shared__ float sm1[];
    float* Xs = sm1;                   // 128*XST
    float* Rs = sm1 + 128 * XST;       // 128*RST
    const int tid = threadIdx.x;       // 128 threads

    for (int idx = tid; idx < 128 * HB; idx += 128) {
        int f = idx / HB, h = idx % HB;
        Rs[f * RST + h] = rot[f * ROTC + h];
    }
    const float* xb = x_msg + ((size_t)b * NN + n0) * FM;
    for (int idx = tid; idx < 128 * FM; idx += 128) {
        int r = idx >> 7, f = idx & 127;
        Xs[r * XST + f] = xb[idx];
    }
    __syncthreads();

    u64 acc[25];
#pragma unroll
    for (int p = 0; p < 25; p++) acc[p] = pack2(0.f, 0.f);

    const float* xr = Xs + tid * XST;
    for (int f4 = 0; f4 < FM; f4 += 4) {
        float4 xq = *(const float4*)(xr + f4);
        float xv4[4] = {xq.x, xq.y, xq.z, xq.w};
#pragma unroll
        for (int ff = 0; ff < 4; ff++) {
            const float* rp = Rs + (f4 + ff) * RST;
            u64 xs2 = pack2(xv4[ff], xv4[ff]);
            const ulonglong2* rq = (const ulonglong2*)rp;  // 16B aligned (RST*4=208)
#pragma unroll
            for (int q = 0; q < 12; q++) {
                ulonglong2 pr = rq[q];
                fma2(acc[2 * q + 0], xs2, pr.x);
                fma2(acc[2 * q + 1], xs2, pr.y);
            }
            u64 tail = *(const u64*)(rp + 48);
            fma2(acc[24], xs2, tail);
        }
    }

    float a[HB];
#pragma unroll
    for (int p = 0; p < 25; p++) unpack2(acc[p], a[2 * p], a[2 * p + 1]);

    // argmax over cmul = [mul, -mul] with first-occurrence tie rule
    float bv = a[0]; int bh = 0;
    float mv = a[0]; int mh = 0;
#pragma unroll
    for (int h = 1; h < HB; h++) {
        if (a[h] > bv) { bv = a[h]; bh = h; }
        if (a[h] < mv) { mv = a[h]; mh = h; }
    }
    int idx = (bv >= -mv) ? bh : (HB + mh);

    const int n = n0 + tid;
    const int m = msk[(size_t)b * NN + n];
    g_key[(size_t)b * NN + n] = idx + (m ? 0 : (NBINS - 1));
}

// ---------------------------------------------------------------------------
// K2: stable counting sort per batch (matches stable jnp.argsort).
// 16 blocks x 128 threads; thread t owns contiguous chunk of 100 items.
// Also writes bins_split (as float) and msk_f_binned directly to d_out.
// ---------------------------------------------------------------------------
__global__ void k_sort(const int* __restrict__ msk,
                       float* __restrict__ out) {
    const int b = blockIdx.x;
    extern __shared__ unsigned short off[];        // [NKEYS][128]
    __shared__ unsigned int keyTotal[NKEYS];
    __shared__ unsigned int keyBase[NKEYS];
    const int t = threadIdx.x;                     // 128 threads

    for (int i = t; i < NKEYS * 128; i += 128) off[i] = 0;
    __syncthreads();

    const int* kb = g_key + (size_t)b * NN;
    const int base_n = t * 100;
    for (int q = 0; q < 100; q++) {
        int k = kb[base_n + q];
        off[k * 128 + t]++;
    }
    __syncthreads();

    for (int k = t; k < NKEYS; k += 128) {
        unsigned int run = 0;
        for (int tt = 0; tt < 128; tt++) {
            unsigned short c = off[k * 128 + tt];
            off[k * 128 + tt] = (unsigned short)run;
            run += c;
        }
        keyTotal[k] = run;
    }
    __syncthreads();
    if (t == 0) {
        unsigned int run = 0;
        for (int k = 0; k < NKEYS; k++) { keyBase[k] = run; run += keyTotal[k]; }
    }
    __syncthreads();

    int* gb = g_bins + (size_t)b * NN;
    const int* mb = msk + (size_t)b * NN;
    float* out_bins = out + OFF_BINS + (size_t)b * NN;
    float* out_mskf = out + OFF_MSKF + (size_t)b * NN;
    for (int q = 0; q < 100; q++) {
        int n = base_n + q;
        int k = kb[n];
        unsigned int pos = keyBase[k] + off[k * 128 + t];
        off[k * 128 + t]++;
        gb[pos] = n;
        out_bins[pos] = (float)n;
        out_mskf[pos] = mb[n] ? 1.0f : 0.0f;
    }
}

// ---------------------------------------------------------------------------
// K4: per-bin pairwise gaussian kernel + fused x_node gather.
// One block (16x16 threads) per (b, bin). A^T staged in smem [f][i] (stride
// 132), gram via 8x8 register tiles with packed fma.rn.f32x2, MUFU epilogue.
// Tail: copies this bin's 128 x_node rows (overlaps other blocks' compute).
// dyn smem: 128*132*4 + 2*128*4 = 68608 B.
// ---------------------------------------------------------------------------
#define ST 132
__global__ void __launch_bounds__(256, 2)
k_dm(const float4* __restrict__ x_msg4,
     const int* __restrict__ msk,
     const float4* __restrict__ x_node4,
     float* __restrict__ out) {
    const int b   = blockIdx.x / NBINS;
    const int bin = blockIdx.x % NBINS;
    extern __shared__ float sm4[];
    float* As = sm4;                 // [128][ST], f-major (A transposed)
    float* na = sm4 + 128 * ST;      // [128]
    float* mm = na + 128;            // [128]
    const int tid  = threadIdx.x;    // 256
    const int w    = tid >> 5;
    const int lane = tid & 31;

    const int* gb = g_bins + ((size_t)b * NBINS + bin) * BS;
    const float4* xb = x_msg4 + (size_t)b * NN * (FM / 4);
    for (int r = w; r < BS; r += 8) {
        int src = gb[r];
        float m = msk[(size_t)b * NN + src] ? 1.f : 0.f;
        float4 v = xb[(size_t)src * (FM / 4) + lane];
        v.x *= m; v.y *= m; v.z *= m; v.w *= m;
        As[(4 * lane + 0) * ST + r] = v.x;
        As[(4 * lane + 1) * ST + r] = v.y;
        As[(4 * lane + 2) * ST + r] = v.z;
        As[(4 * lane + 3) * ST + r] = v.w;
        float s = v.x * v.x + v.y * v.y + v.z * v.z + v.w * v.w;
#pragma unroll
        for (int o = 16; o; o >>= 1) s += __shfl_xor_sync(0xffffffffu, s, o);
        if (lane == 0) { na[r] = s; mm[r] = m; }
    }
    __syncthreads();

    const int tx = tid & 15, ty = tid >> 4;
    const int i0 = ty * 8, j0 = tx * 8;
    u64 acc2[8][4];
#pragma unroll
    for (int u = 0; u < 8; u++)
#pragma unroll
        for (int v = 0; v < 4; v++) acc2[u][v] = pack2(0.f, 0.f);

    for (int f = 0; f < FM; f++) {
        const float* row = As + f * ST;
        float4 a0 = *(const float4*)(row + i0);
        float4 a1 = *(const float4*)(row + i0 + 4);
        ulonglong2 q0 = *(const ulonglong2*)(row + j0);      // pairs (j0,j0+1),(j0+2,j0+3)
        ulonglong2 q1 = *(const ulonglong2*)(row + j0 + 4);
        float a[8] = {a0.x, a0.y, a0.z, a0.w, a1.x, a1.y, a1.z, a1.w};
        u64 bq[4] = {q0.x, q0.y, q1.x, q1.y};
#pragma unroll
        for (int u = 0; u < 8; u++) {
            u64 au = pack2(a[u], a[u]);
#pragma unroll
            for (int v = 0; v < 4; v++) fma2(acc2[u][v], au, bq[v]);
        }
    }

    float nai[8], mi[8], naj[8], mj[8];
#pragma unroll
    for (int u = 0; u < 8; u++) { nai[u] = na[i0 + u]; mi[u] = mm[i0 + u]; }
#pragma unroll
    for (int v = 0; v < 8; v++) { naj[v] = na[j0 + v]; mj[v] = mm[j0 + v]; }

    float* dout = out + OFF_DM + (size_t)blockIdx.x * BS * BS;
    const float c = -0.14426950408889634f;   // -DIST_MULT * log2(e)
#pragma unroll
    for (int u = 0; u < 8; u++) {
        float g[8];
#pragma unroll
        for (int v = 0; v < 4; v++) unpack2(acc2[u][v], g[2 * v], g[2 * v + 1]);
        float res[8];
#pragma unroll
        for (int v = 0; v < 8; v++) {
            float x = fmaxf(nai[u] + naj[v] - 2.0f * g[v], 1e-6f);
            float d = x * rsqf(x);            // sqrt(x), x >= 1e-6
            float val = ex2f(c * d) * mi[u] * mj[v];
            res[v] = fminf(val, 1.0f);
        }
        float4* p = (float4*)(dout + (i0 + u) * BS + j0);
        p[0] = make_float4(res[0], res[1], res[2], res[3]);
        p[1] = make_float4(res[4], res[5], res[6], res[7]);
    }

    // Fused x_node gather: this bin's 128 rows of 256 floats (64 float4).
    const float4* xn = x_node4 + (size_t)b * NN * (FN / 4);
    float4* xo = (float4*)(out + OFF_XNODE) + (size_t)blockIdx.x * BS * (FN / 4);
    for (int r = w; r < BS; r += 8) {
        int src = gb[r];
        const float4* s = xn + (size_t)src * (FN / 4);
        float4* d = xo + (size_t)r * (FN / 4);
#pragma unroll
        for (int c4 = 0; c4 < 2; c4++) d[lane + 32 * c4] = s[lane + 32 * c4];
    }
}

// ---------------------------------------------------------------------------
extern "C" void kernel_launch(void* const* d_in, const int* in_sizes, int n_in,
                              void* d_out, int out_size) {
    const float* x_msg  = (const float*)d_in[0];
    const float* x_node = (const float*)d_in[1];
    const int*   msk    = (const int*)d_in[2];
    const float* rot    = (const float*)d_in[3];
    float* out = (float*)d_out;

    const int SM1 = 128 * XST * 4 + 128 * RST * 4;  // 94208
    const int SM2 = NKEYS * 128 * 2;                // 51200
    const int SM4 = 128 * ST * 4 + 2 * 128 * 4;     // 68608
    cudaFuncSetAttribute(k_proj, cudaFuncAttributeMaxDynamicSharedMemorySize, SM1);
    cudaFuncSetAttribute(k_sort, cudaFuncAttributeMaxDynamicSharedMemorySize, SM2);
    cudaFuncSetAttribute(k_dm,   cudaFuncAttributeMaxDynamicSharedMemorySize, SM4);

    k_proj<<<BB * (NN / 128), 128, SM1>>>(x_msg, msk, rot);
    k_sort<<<BB, 128, SM2>>>(msk, out);
    k_dm<<<BB * NBINS, 256, SM4>>>((const float4*)x_msg, msk,
                                   (const float4*)x_node, out);
}